// round 1
// baseline (speedup 1.0000x reference)
#include <cuda_runtime.h>

#define NTHREADS 128
#define TILE_W 256
#define TILE_H 128
#define IMG_H 1024
#define IMG_W 1024
#define NBATCH 32
#define NPIX (32.0f * 1024.0f * 1024.0f)

__device__ float g_accum;

__global__ void k_zero() { g_accum = 0.0f; }

__device__ __forceinline__ void fma4(float4& a, float w, const float4& v) {
    a.x = fmaf(w, v.x, a.x);
    a.y = fmaf(w, v.y, a.y);
    a.z = fmaf(w, v.z, a.z);
    a.w = fmaf(w, v.w, a.w);
}

__device__ __forceinline__ float ssim_val(const float4& a) {
    // a = (A, B, P, Q) = (conv(s), conv(d), conv(s^2), conv(d^2))
    // 2*mu1*mu2          = (A^2 - B^2)/2
    // mu1^2 + mu2^2      = (A^2 + B^2)/2
    // 2*conv(i1*i2)      = (P - Q)/2
    // conv(i1^2 + i2^2)  = (P + Q)/2
    const float C1v = 0.0001f;   // 0.01^2
    const float C2v = 0.0009f;   // 0.03^2
    float A2 = a.x * a.x;
    float B2 = a.y * a.y;
    float cross = 0.5f * (A2 - B2);
    float sums  = 0.5f * (A2 + B2);
    float t12   = 0.5f * (a.z - a.w);
    float tss   = 0.5f * (a.z + a.w);
    float num = (cross + C1v) * (t12 - cross + C2v);
    float den = (sums  + C1v) * (tss - sums  + C2v);
    return __fdividef(num, den);
}

// Normalized 11-tap Gaussian, sigma=1.5 (matches numpy reference to ~3e-7)
#define GW0 0.00102838f
#define GW1 0.00759878f
#define GW2 0.03600077f
#define GW3 0.10936072f
#define GW4 0.21300560f
#define GW5 0.26601180f

__global__ __launch_bounds__(NTHREADS)
void k_ssim(const float* __restrict__ img1, const float* __restrict__ img2) {
    __shared__ float4 raw[2][272];
    __shared__ float wpart[NTHREADS / 32];

    const float GW[11] = { GW0, GW1, GW2, GW3, GW4, GW5, GW4, GW3, GW2, GW1, GW0 };

    const int tid = threadIdx.x;
    const int x0 = blockIdx.x * TILE_W;
    const int y0 = blockIdx.y * TILE_H;
    const long ofs = (long)blockIdx.z * (long)(IMG_H * IMG_W);
    const float* p1 = img1 + ofs;
    const float* p2 = img2 + ofs;

    // vertical accumulator rings (register-resident, static indices after unroll)
    float4 acc0[11], acc1[11];
#pragma unroll
    for (int j = 0; j < 11; ++j) {
        acc0[j] = make_float4(0.f, 0.f, 0.f, 0.f);
        acc1[j] = make_float4(0.f, 0.f, 0.f, 0.f);
    }

    float ssum = 0.0f;
    const int base = 2 * tid;
    const int steps = TILE_H + 10;  // 138

    for (int ib = 0; ib < steps; ib += 11) {
#pragma unroll
        for (int m = 0; m < 11; ++m) {
            const int i = ib + m;
            if (i < steps) {   // uniform across the block
                const int buf = i & 1;
                const int ry = y0 - 5 + i;
                const bool rowok = ((unsigned)ry < (unsigned)IMG_H);
                const float* r1 = p1 + (long)ry * IMG_W;
                const float* r2 = p2 + (long)ry * IMG_W;

                // stage one raw input row (with halo + zero padding) into smem
#pragma unroll
                for (int c0 = 0; c0 < 3; ++c0) {
                    int c = tid + c0 * NTHREADS;
                    if (c < TILE_W + 10) {
                        int x = x0 - 5 + c;
                        float a = 0.f, b = 0.f;
                        if (rowok && (unsigned)x < (unsigned)IMG_W) {
                            a = __ldg(r1 + x);
                            b = __ldg(r2 + x);
                        }
                        float s = a + b;
                        float d = a - b;
                        raw[buf][c] = make_float4(s, d, s * s, d * d);
                    }
                }
                __syncthreads();

                // horizontal 11-tap conv for two adjacent columns (taps shared)
                float4 h0 = make_float4(0.f, 0.f, 0.f, 0.f);
                float4 h1 = make_float4(0.f, 0.f, 0.f, 0.f);
#pragma unroll
                for (int k = 0; k < 11; ++k) {
                    float4 v = raw[buf][base + k];
                    fma4(h0, GW[k], v);
                    if (k >= 1) fma4(h1, GW[k - 1], v);
                }
                {
                    float4 v = raw[buf][base + 11];
                    fma4(h1, GW[10], v);
                }

                // scatter this h-row into the 11 vertical accumulators
#pragma unroll
                for (int j = 0; j < 11; ++j) {
                    const int o = i - 10 + j;           // output row receiving weight GW[10-j]
                    const int slot = (m + j + 1) % 11;  // == o % 11 (compile-time)
                    if (o >= 0 && o < TILE_H) {
                        const float w = GW[10 - j];
                        fma4(acc0[slot], w, h0);
                        fma4(acc1[slot], w, h1);
                    }
                }

                // output row (i-10) is now complete
                if (i >= 10) {
                    const int se = (m + 1) % 11;        // == (i-10) % 11
                    ssum += ssim_val(acc0[se]);
                    ssum += ssim_val(acc1[se]);
                    acc0[se] = make_float4(0.f, 0.f, 0.f, 0.f);
                    acc1[se] = make_float4(0.f, 0.f, 0.f, 0.f);
                }
            }
        }
    }

    // block reduction -> one atomic per CTA
#pragma unroll
    for (int off = 16; off > 0; off >>= 1)
        ssum += __shfl_xor_sync(0xffffffffu, ssum, off);
    if ((tid & 31) == 0) wpart[tid >> 5] = ssum;
    __syncthreads();
    if (tid == 0)
        atomicAdd(&g_accum, wpart[0] + wpart[1] + wpart[2] + wpart[3]);
}

__global__ void k_final(float* out) {
    out[0] = 1.0f - g_accum * (1.0f / NPIX);
}

extern "C" void kernel_launch(void* const* d_in, const int* in_sizes, int n_in,
                              void* d_out, int out_size) {
    const float* img1 = (const float*)d_in[0];
    const float* img2 = (const float*)d_in[1];
    float* out = (float*)d_out;

    k_zero<<<1, 1>>>();
    dim3 grid(IMG_W / TILE_W, IMG_H / TILE_H, NBATCH);
    k_ssim<<<grid, NTHREADS>>>(img1, img2);
    k_final<<<1, 1>>>(out);
}

// round 2
// speedup vs baseline: 1.7928x; 1.7928x over previous
#include <cuda_runtime.h>

typedef unsigned long long u64;
typedef unsigned int u32;

#define NTH 256
#define TILE_W 256
#define TILE_H 128
#define IMG 1024
#define NBATCH 32
#define STEPS (TILE_H + 10)
#define HALF_STRIDE 280           // u64 units; 280*8 = 2240 B == 64 mod 128 -> bank-disjoint halves
#define NPIX (32.0f * 1024.0f * 1024.0f)

__device__ float g_accum;
__global__ void k_zero() { g_accum = 0.0f; }

// Normalized 11-tap Gaussian, sigma=1.5
#define W0 0.00102838f
#define W1 0.00759878f
#define W2 0.03600077f
#define W3 0.10936072f
#define W4 0.21300560f
#define W5 0.26601180f

__device__ __forceinline__ u64 pack2(float lo, float hi) {
    u64 r;
    asm("mov.b64 %0, {%1,%2};" : "=l"(r) : "f"(lo), "f"(hi));
    return r;
}
__device__ __forceinline__ void unpack2(u64 v, float& lo, float& hi) {
    asm("mov.b64 {%0,%1}, %2;" : "=f"(lo), "=f"(hi) : "l"(v));
}
// d = a * b + c  on packed f32x2 (sm_103a FFMA2 — only reachable via PTX)
__device__ __forceinline__ u64 ffma2(u64 a, u64 b, u64 c) {
    u64 d;
    asm("fma.rn.f32x2 %0, %1, %2, %3;" : "=l"(d) : "l"(a), "l"(b), "l"(c));
    return d;
}
// 16B vector load of two packed f32x2 from shared
__device__ __forceinline__ void lds2(u32 addr, u64& a, u64& b) {
    asm volatile("ld.shared.v2.u64 {%0,%1}, [%2];" : "=l"(a), "=l"(b) : "r"(addr));
}

__global__ __launch_bounds__(NTH, 2)
void k_ssim(const float* __restrict__ img1, const float* __restrict__ img2) {
    // [buf][half][col] : 2 * 2 * 280 u64 = 8960 B
    __shared__ __align__(16) u64 raw[2 * 2 * HALF_STRIDE];
    __shared__ float wpart[NTH / 32];

    u32 sbase;
    asm("{ .reg .u64 t; cvta.to.shared.u64 t, %1; cvt.u32.u64 %0, t; }"
        : "=r"(sbase) : "l"(raw));

    const int tid  = threadIdx.x;
    const int half = tid & 1;        // 0: (s,d) plane, 1: (s^2,d^2) plane
    const int p    = tid >> 1;       // column pair index, cols 2p, 2p+1
    const int x0 = blockIdx.x * TILE_W;
    const int y0 = blockIdx.y * TILE_H;
    const size_t ofs = (size_t)blockIdx.z * (size_t)(IMG * IMG);
    const float* p1 = img1 + ofs;
    const float* p2 = img2 + ofs;

    // packed gaussian weights (symmetric)
    const u64 GW[11] = {
        pack2(W0, W0), pack2(W1, W1), pack2(W2, W2), pack2(W3, W3), pack2(W4, W4),
        pack2(W5, W5),
        pack2(W4, W4), pack2(W3, W3), pack2(W2, W2), pack2(W1, W1), pack2(W0, W0)
    };

    // staging: columns (tile-relative, 0 .. TILE_W+9 map to image x0-5 .. x0+TILE_W+4)
    const int c1 = tid;
    const int c2 = tid + NTH;
    const bool act2 = (c2 < TILE_W + 10);
    const int gx1 = x0 - 5 + c1;
    const int gx2 = x0 - 5 + c2;
    const bool okx1 = ((unsigned)gx1 < (unsigned)IMG);
    const bool okx2 = act2 && ((unsigned)gx2 < (unsigned)IMG);

    u64 ring0[11], ring1[11];   // vertical sliding windows for cols 2p, 2p+1

    float ssum = 0.0f;

    // prefetch row 0 (ry = y0 - 5)
    float a1, b1, a2, b2;
    {
        int ry = y0 - 5;
        bool oky = ((unsigned)ry < (unsigned)IMG);
        const float* r1 = p1 + (size_t)ry * IMG;
        const float* r2 = p2 + (size_t)ry * IMG;
        a1 = (oky && okx1) ? __ldg(r1 + gx1) : 0.0f;
        b1 = (oky && okx1) ? __ldg(r2 + gx1) : 0.0f;
        a2 = (oky && okx2) ? __ldg(r1 + gx2) : 0.0f;
        b2 = (oky && okx2) ? __ldg(r2 + gx2) : 0.0f;
    }

    for (int ib = 0; ib < STEPS; ib += 11) {
#pragma unroll
        for (int m = 0; m < 11; ++m) {
            const int i = ib + m;
            if (i < STEPS) {            // uniform across block
                const int buf = i & 1;
                // ---- stage row i from prefetch registers ----
                {
                    float s = a1 + b1, d = a1 - b1;
                    raw[buf * (2 * HALF_STRIDE) + 0 * HALF_STRIDE + c1] = pack2(s, d);
                    raw[buf * (2 * HALF_STRIDE) + 1 * HALF_STRIDE + c1] = pack2(s * s, d * d);
                    if (act2) {
                        float s2 = a2 + b2, d2 = a2 - b2;
                        raw[buf * (2 * HALF_STRIDE) + 0 * HALF_STRIDE + c2] = pack2(s2, d2);
                        raw[buf * (2 * HALF_STRIDE) + 1 * HALF_STRIDE + c2] = pack2(s2 * s2, d2 * d2);
                    }
                }
                __syncthreads();
                // ---- prefetch row i+1 (latency hides under conv below) ----
                {
                    int ry = y0 - 5 + i + 1;
                    bool oky = ((unsigned)ry < (unsigned)IMG) && (i + 1 < STEPS);
                    const float* r1 = p1 + (size_t)ry * IMG;
                    const float* r2 = p2 + (size_t)ry * IMG;
                    a1 = (oky && okx1) ? __ldg(r1 + gx1) : 0.0f;
                    b1 = (oky && okx1) ? __ldg(r2 + gx1) : 0.0f;
                    a2 = (oky && okx2) ? __ldg(r1 + gx2) : 0.0f;
                    b2 = (oky && okx2) ? __ldg(r2 + gx2) : 0.0f;
                }
                // ---- horizontal 11-tap conv, 2 columns (taps shared) ----
                u64 t[12];
                const u32 base = sbase + (u32)((buf * (2 * HALF_STRIDE) + half * HALF_STRIDE + 2 * p) * 8);
#pragma unroll
                for (int k = 0; k < 6; ++k)
                    lds2(base + k * 16u, t[2 * k], t[2 * k + 1]);
                u64 h0 = 0ull, h1 = 0ull;
#pragma unroll
                for (int u = 0; u < 11; ++u) {
                    h0 = ffma2(t[u],     GW[u], h0);
                    h1 = ffma2(t[u + 1], GW[u], h1);
                }
                ring0[m] = h0;          // slot = i % 11 == m (ib multiple of 11)
                ring1[m] = h1;

                // ---- vertical conv + SSIM when window full ----
                if (i >= 10) {
                    u64 v0 = 0ull, v1 = 0ull;
#pragma unroll
                    for (int j = 0; j < 11; ++j) {
                        const int s = (m + 1 + j) % 11;   // slot of row (i-10+j)
                        v0 = ffma2(ring0[s], GW[j], v0);
                        v1 = ffma2(ring1[s], GW[j], v1);
                    }
                    // exchange halves: partner lane differs in bit 0
                    u64 w0 = __shfl_xor_sync(0xffffffffu, v0, 1);
                    u64 w1 = __shfl_xor_sync(0xffffffffu, v1, 1);
                    // half0 computes pixel col 2p: AB=v0, PQ=w0
                    // half1 computes pixel col 2p+1: AB=w1, PQ=v1
                    u64 ab = half ? w1 : v0;
                    u64 pq = half ? v1 : w0;
                    float A, B, P, Q;
                    unpack2(ab, A, B);
                    unpack2(pq, P, Q);
                    float A2 = A * A, B2 = B * B;
                    float cross = 0.5f * (A2 - B2);       // 2*mu1*mu2
                    float sums  = 0.5f * (A2 + B2);       // mu1^2 + mu2^2
                    float t12   = 0.5f * (P - Q);         // 2*conv(i1*i2)
                    float tss   = 0.5f * (P + Q);         // conv(i1^2 + i2^2)
                    float num = (cross + 1e-4f) * (t12 - cross + 9e-4f);
                    float den = (sums  + 1e-4f) * (tss - sums  + 9e-4f);
                    ssum += __fdividef(num, den);
                }
            }
        }
    }

    // block reduction -> one atomic per CTA
#pragma unroll
    for (int off = 16; off > 0; off >>= 1)
        ssum += __shfl_xor_sync(0xffffffffu, ssum, off);
    if ((tid & 31) == 0) wpart[tid >> 5] = ssum;
    __syncthreads();
    if (tid == 0) {
        float acc = 0.0f;
#pragma unroll
        for (int w = 0; w < NTH / 32; ++w) acc += wpart[w];
        atomicAdd(&g_accum, acc);
    }
}

__global__ void k_final(float* out) {
    out[0] = 1.0f - g_accum * (1.0f / NPIX);
}

extern "C" void kernel_launch(void* const* d_in, const int* in_sizes, int n_in,
                              void* d_out, int out_size) {
    const float* img1 = (const float*)d_in[0];
    const float* img2 = (const float*)d_in[1];
    float* out = (float*)d_out;

    k_zero<<<1, 1>>>();
    dim3 grid(IMG / TILE_W, IMG / TILE_H, NBATCH);
    k_ssim<<<grid, NTH>>>(img1, img2);
    k_final<<<1, 1>>>(out);
}